// round 1
// baseline (speedup 1.0000x reference)
#include <cuda_runtime.h>
#include <math.h>

#define POINCARE_BOUND 0.99999f   // 1 - 1e-5

// ---------------------------------------------------------------------------
// helpers (all fully-inlined; arrays must stay register-resident via unroll)
// ---------------------------------------------------------------------------

template<int D>
__device__ __forceinline__ void logmap0_inplace(float* v) {
    float ss = 0.f;
#pragma unroll
    for (int i = 0; i < D; ++i) ss = fmaf(v[i], v[i], ss);
    float n = fmaxf(sqrtf(ss), 1e-15f);
    float s = atanhf(fminf(n, POINCARE_BOUND)) / n;
#pragma unroll
    for (int i = 0; i < D; ++i) v[i] *= s;
}

template<int D>
__device__ __forceinline__ void expmap0_inplace(float* v) {
    float ss = 0.f;
#pragma unroll
    for (int i = 0; i < D; ++i) ss = fmaf(v[i], v[i], ss);
    float n = fmaxf(sqrtf(ss), 1e-15f);
    float s = tanhf(n) / n;
#pragma unroll
    for (int i = 0; i < D; ++i) v[i] *= s;
}

// o = mobius_add(x, y); o may alias x. y may point to shared memory.
template<int D>
__device__ __forceinline__ void mobius_add(const float* x, const float* y, float* o) {
    float x2 = 0.f, y2 = 0.f, xy = 0.f;
#pragma unroll
    for (int i = 0; i < D; ++i) {
        x2 = fmaf(x[i], x[i], x2);
        y2 = fmaf(y[i], y[i], y2);
        xy = fmaf(x[i], y[i], xy);
    }
    float a   = 1.f + 2.f * xy + y2;   // coeff of x
    float b   = 1.f - x2;              // coeff of y
    float den = 1.f + 2.f * xy + x2 * y2;
    den = fmaxf(den, 1e-15f);
    float inv = 1.f / den;
#pragma unroll
    for (int i = 0; i < D; ++i) o[i] = (a * x[i] + b * y[i]) * inv;
}

// o[OUT] = v[IN] @ W[IN][OUT]   (W in shared, row-major, float4-vectorized)
template<int IN, int OUT>
__device__ __forceinline__ void matvec(const float* v, const float* sW, float* o) {
#pragma unroll
    for (int j = 0; j < OUT; ++j) o[j] = 0.f;
#pragma unroll
    for (int k = 0; k < IN; ++k) {
        const float vk = v[k];
        const float4* wr = reinterpret_cast<const float4*>(sW + k * OUT);
#pragma unroll
        for (int j = 0; j < OUT / 4; ++j) {
            float4 w = wr[j];
            o[4 * j + 0] = fmaf(vk, w.x, o[4 * j + 0]);
            o[4 * j + 1] = fmaf(vk, w.y, o[4 * j + 1]);
            o[4 * j + 2] = fmaf(vk, w.z, o[4 * j + 2]);
            o[4 * j + 3] = fmaf(vk, w.w, o[4 * j + 3]);
        }
    }
}

// load one 32-wide row and apply logmap0
__device__ __forceinline__ void load_log32(const float* __restrict__ gx, int row, float* u) {
    const float4* xp = reinterpret_cast<const float4*>(gx + (size_t)row * 32);
    float ss = 0.f;
#pragma unroll
    for (int i = 0; i < 8; ++i) {
        float4 v = xp[i];
        u[4 * i + 0] = v.x; u[4 * i + 1] = v.y;
        u[4 * i + 2] = v.z; u[4 * i + 3] = v.w;
        ss = fmaf(v.x, v.x, ss); ss = fmaf(v.y, v.y, ss);
        ss = fmaf(v.z, v.z, ss); ss = fmaf(v.w, v.w, ss);
    }
    float n = fmaxf(sqrtf(ss), 1e-15f);
    float s = atanhf(fminf(n, POINCARE_BOUND)) / n;
#pragma unroll
    for (int i = 0; i < 32; ++i) u[i] *= s;
}

// ---------------------------------------------------------------------------
// kernel: one thread per row; all weights staged in shared memory
// ---------------------------------------------------------------------------

__global__ void __launch_bounds__(256)
poincare_mlp_kernel(const float* __restrict__ gx1,
                    const float* __restrict__ gx2,
                    const float* __restrict__ gWc1,
                    const float* __restrict__ gWc2,
                    const float* __restrict__ gbc,
                    const float* __restrict__ gW0,
                    const float* __restrict__ gb0,
                    const float* __restrict__ gW1,
                    const float* __restrict__ gb1,
                    float* __restrict__ gout,
                    int N)
{
    __shared__ float sWc1[32 * 64];
    __shared__ float sWc2[32 * 64];
    __shared__ float sW0 [64 * 64];
    __shared__ float sW1 [64 * 32];
    __shared__ float sbc [64];
    __shared__ float sb0 [64];
    __shared__ float sb1 [32];

    const int tid = threadIdx.x;
#pragma unroll 1
    for (int i = tid; i < 2048; i += 256) {
        sWc1[i] = gWc1[i];
        sWc2[i] = gWc2[i];
        sW1 [i] = gW1 [i];
    }
#pragma unroll 1
    for (int i = tid; i < 4096; i += 256) sW0[i] = gW0[i];
    if (tid < 64) { sbc[tid] = gbc[tid]; sb0[tid] = gb0[tid]; }
    if (tid < 32) { sb1[tid] = gb1[tid]; }
    __syncthreads();

    const int row = blockIdx.x * 256 + tid;
    if (row >= N) return;

    float u[32];
    float h1[64];
    float h2[64];

    // ---- branch 1: h1 = expmap0(logmap0(x1) @ Wc1)
    load_log32(gx1, row, u);
    matvec<32, 64>(u, sWc1, h1);
    expmap0_inplace<64>(h1);

    // ---- branch 2: h2 = expmap0(logmap0(x2) @ Wc2)
    load_log32(gx2, row, u);
    matvec<32, 64>(u, sWc2, h2);
    expmap0_inplace<64>(h2);

    // ---- h = mobius_add(mobius_add(h1, h2), bc)
    float h[64];
    mobius_add<64>(h1, h2, h);
    mobius_add<64>(h, sbc, h1);          // h1 <- concat output

    // ---- layer 0: mobius_add(expmap0(logmap0(h) @ W0), b0)
    logmap0_inplace<64>(h1);
    matvec<64, 64>(h1, sW0, h2);
    expmap0_inplace<64>(h2);
    mobius_add<64>(h2, sb0, h1);         // h1 <- layer0 output

    // ---- layer 1: mobius_add(expmap0(logmap0(h) @ W1), b1)
    logmap0_inplace<64>(h1);
    float o[32];
    matvec<64, 32>(h1, sW1, o);
    expmap0_inplace<32>(o);
    float ov[32];
    mobius_add<32>(o, sb1, ov);

    float4* op = reinterpret_cast<float4*>(gout + (size_t)row * 32);
#pragma unroll
    for (int i = 0; i < 8; ++i)
        op[i] = make_float4(ov[4 * i + 0], ov[4 * i + 1], ov[4 * i + 2], ov[4 * i + 3]);
}

// ---------------------------------------------------------------------------
// launch
// ---------------------------------------------------------------------------

extern "C" void kernel_launch(void* const* d_in, const int* in_sizes, int n_in,
                              void* d_out, int out_size)
{
    const float* x1  = (const float*)d_in[0];
    const float* x2  = (const float*)d_in[1];
    const float* Wc1 = (const float*)d_in[2];
    const float* Wc2 = (const float*)d_in[3];
    const float* bc  = (const float*)d_in[4];
    const float* W0  = (const float*)d_in[5];
    const float* b0  = (const float*)d_in[6];
    const float* W1  = (const float*)d_in[7];
    const float* b1  = (const float*)d_in[8];
    float* out = (float*)d_out;

    const int N = in_sizes[0] / 32;
    const int blocks = (N + 255) / 256;
    poincare_mlp_kernel<<<blocks, 256>>>(x1, x2, Wc1, Wc2, bc, W0, b0, W1, b1, out, N);
}

// round 2
// speedup vs baseline: 1.6131x; 1.6131x over previous
#include <cuda_runtime.h>
#include <math.h>

#define POINCARE_BOUND 0.99999f   // 1 - 1e-5

typedef unsigned long long u64;

// ---------------------------------------------------------------------------
// constant-memory weights (uniform across all threads -> LDCU uniform port)
// ---------------------------------------------------------------------------
__constant__ float cWc1[32 * 64];
__constant__ float cWc2[32 * 64];
__constant__ float cW0 [64 * 64];
__constant__ float cW1 [64 * 32];
__constant__ float cbc [64];
__constant__ float cb0 [64];
__constant__ float cb1 [32];

// ---------------------------------------------------------------------------
// packed f32x2 helpers (Blackwell dual-FMA: fma.rn.f32x2)
// ---------------------------------------------------------------------------
__device__ __forceinline__ u64 pk2(float lo, float hi) {
    u64 r; asm("mov.b64 %0, {%1, %2};" : "=l"(r) : "f"(lo), "f"(hi)); return r;
}
__device__ __forceinline__ void upk2(u64 v, float& lo, float& hi) {
    asm("mov.b64 {%0, %1}, %2;" : "=f"(lo), "=f"(hi) : "l"(v));
}
__device__ __forceinline__ u64 fma2(u64 a, u64 b, u64 c) {
    u64 d; asm("fma.rn.f32x2 %0, %1, %2, %3;" : "=l"(d) : "l"(a), "l"(b), "l"(c)); return d;
}

// ---------------------------------------------------------------------------
// math helpers
// ---------------------------------------------------------------------------
template<int D>
__device__ __forceinline__ void logmap0_inplace(float* v) {
    float ss = 0.f;
#pragma unroll
    for (int i = 0; i < D; ++i) ss = fmaf(v[i], v[i], ss);
    float n = fmaxf(sqrtf(ss), 1e-15f);
    float s = atanhf(fminf(n, POINCARE_BOUND)) / n;
#pragma unroll
    for (int i = 0; i < D; ++i) v[i] *= s;
}

template<int D>
__device__ __forceinline__ void expmap0_inplace(float* v) {
    float ss = 0.f;
#pragma unroll
    for (int i = 0; i < D; ++i) ss = fmaf(v[i], v[i], ss);
    float n = fmaxf(sqrtf(ss), 1e-15f);
    float s = tanhf(n) / n;
#pragma unroll
    for (int i = 0; i < D; ++i) v[i] *= s;
}

// o = mobius_add(x, y); y may be constant-memory
template<int D>
__device__ __forceinline__ void mobius_add(const float* x, const float* y, float* o) {
    float x2 = 0.f, y2 = 0.f, xy = 0.f;
#pragma unroll
    for (int i = 0; i < D; ++i) {
        x2 = fmaf(x[i], x[i], x2);
        y2 = fmaf(y[i], y[i], y2);
        xy = fmaf(x[i], y[i], xy);
    }
    float a   = 1.f + 2.f * xy + y2;
    float b   = 1.f - x2;
    float den = 1.f + 2.f * xy + x2 * y2;
    den = fmaxf(den, 1e-15f);
    float inv = 1.f / den;
#pragma unroll
    for (int i = 0; i < D; ++i) o[i] = (a * x[i] + b * y[i]) * inv;
}

// o[OUT] = v[IN] @ W[IN][OUT], W in __constant__ (uniform), f32x2 packed FMAs
template<int IN, int OUT>
__device__ __forceinline__ void matvecC(const float* v, const float* cW, float* o) {
    u64 acc[OUT / 2];
#pragma unroll
    for (int j = 0; j < OUT / 2; ++j) acc[j] = 0ull;
#pragma unroll
    for (int k = 0; k < IN; ++k) {
        const u64 vv = pk2(v[k], v[k]);
        const u64* wr = reinterpret_cast<const u64*>(cW + k * OUT);
#pragma unroll
        for (int j = 0; j < OUT / 2; ++j)
            acc[j] = fma2(vv, wr[j], acc[j]);
    }
#pragma unroll
    for (int j = 0; j < OUT / 2; ++j)
        upk2(acc[j], o[2 * j], o[2 * j + 1]);
}

// load one 32-wide row and apply logmap0
__device__ __forceinline__ void load_log32(const float* __restrict__ gx, int row, float* u) {
    const float4* xp = reinterpret_cast<const float4*>(gx + (size_t)row * 32);
    float ss = 0.f;
#pragma unroll
    for (int i = 0; i < 8; ++i) {
        float4 v = xp[i];
        u[4 * i + 0] = v.x; u[4 * i + 1] = v.y;
        u[4 * i + 2] = v.z; u[4 * i + 3] = v.w;
        ss = fmaf(v.x, v.x, ss); ss = fmaf(v.y, v.y, ss);
        ss = fmaf(v.z, v.z, ss); ss = fmaf(v.w, v.w, ss);
    }
    float n = fmaxf(sqrtf(ss), 1e-15f);
    float s = atanhf(fminf(n, POINCARE_BOUND)) / n;
#pragma unroll
    for (int i = 0; i < 32; ++i) u[i] *= s;
}

// ---------------------------------------------------------------------------
// kernel: one thread per row; weights in constant memory; no shared, no sync
// ---------------------------------------------------------------------------
__global__ void __launch_bounds__(128, 3)
poincare_mlp_kernel(const float* __restrict__ gx1,
                    const float* __restrict__ gx2,
                    float* __restrict__ gout,
                    int N)
{
    const int row = blockIdx.x * 128 + threadIdx.x;
    if (row >= N) return;

    float u[32];
    float h1[64];
    float h2[64];

    // ---- branch 1: h1 = expmap0(logmap0(x1) @ Wc1)
    load_log32(gx1, row, u);
    matvecC<32, 64>(u, cWc1, h1);
    expmap0_inplace<64>(h1);

    // ---- branch 2: h2 = expmap0(logmap0(x2) @ Wc2)
    load_log32(gx2, row, u);
    matvecC<32, 64>(u, cWc2, h2);
    expmap0_inplace<64>(h2);

    // ---- h = mobius_add(mobius_add(h1, h2), bc)
    float h[64];
    mobius_add<64>(h1, h2, h);
    mobius_add<64>(h, cbc, h1);          // h1 <- concat output

    // ---- layer 0: mobius_add(expmap0(logmap0(h) @ W0), b0)
    logmap0_inplace<64>(h1);
    matvecC<64, 64>(h1, cW0, h2);
    expmap0_inplace<64>(h2);
    mobius_add<64>(h2, cb0, h1);         // h1 <- layer0 output

    // ---- layer 1: mobius_add(expmap0(logmap0(h) @ W1), b1)
    logmap0_inplace<64>(h1);
    float o[32];
    matvecC<64, 32>(h1, cW1, o);
    expmap0_inplace<32>(o);
    float ov[32];
    mobius_add<32>(o, cb1, ov);

    float4* op = reinterpret_cast<float4*>(gout + (size_t)row * 32);
#pragma unroll
    for (int i = 0; i < 8; ++i)
        op[i] = make_float4(ov[4 * i + 0], ov[4 * i + 1], ov[4 * i + 2], ov[4 * i + 3]);
}

// ---------------------------------------------------------------------------
// launch
// ---------------------------------------------------------------------------
extern "C" void kernel_launch(void* const* d_in, const int* in_sizes, int n_in,
                              void* d_out, int out_size)
{
    const float* x1 = (const float*)d_in[0];
    const float* x2 = (const float*)d_in[1];

    // stage weights into constant memory (D2D async copies — graph-capturable)
    cudaMemcpyToSymbolAsync(cWc1, d_in[2], 32 * 64 * sizeof(float), 0, cudaMemcpyDeviceToDevice);
    cudaMemcpyToSymbolAsync(cWc2, d_in[3], 32 * 64 * sizeof(float), 0, cudaMemcpyDeviceToDevice);
    cudaMemcpyToSymbolAsync(cbc,  d_in[4], 64 * sizeof(float),      0, cudaMemcpyDeviceToDevice);
    cudaMemcpyToSymbolAsync(cW0,  d_in[5], 64 * 64 * sizeof(float), 0, cudaMemcpyDeviceToDevice);
    cudaMemcpyToSymbolAsync(cb0,  d_in[6], 64 * sizeof(float),      0, cudaMemcpyDeviceToDevice);
    cudaMemcpyToSymbolAsync(cW1,  d_in[7], 64 * 32 * sizeof(float), 0, cudaMemcpyDeviceToDevice);
    cudaMemcpyToSymbolAsync(cb1,  d_in[8], 32 * sizeof(float),      0, cudaMemcpyDeviceToDevice);

    float* out = (float*)d_out;
    const int N = in_sizes[0] / 32;
    const int blocks = (N + 127) / 128;
    poincare_mlp_kernel<<<blocks, 128>>>(x1, x2, out, N);
}